// round 1
// baseline (speedup 1.0000x reference)
#include <cuda_runtime.h>
#include <math.h>

#define Bq    2
#define Sq    2048
#define Dq    1024
#define Hq    16
#define KVHq  4
#define HDq   64
#define QLATq 64
#define KVLATq 32
#define Eq    8
#define FFq   4096
#define NTOK  (Bq*Sq)      // 4096
#define NSLOT (NTOK*2)     // 8192

// ---------------- scratch (device globals; no allocations) ----------------
__device__ float g_h     [(size_t)NTOK*Dq];
__device__ float g_qlat  [(size_t)NTOK*QLATq];
__device__ float g_q     [(size_t)NTOK*Dq];
__device__ float g_kvlat [(size_t)NTOK*KVLATq];
__device__ float g_kvfull[(size_t)NTOK*512];
__device__ float g_k     [(size_t)NTOK*KVHq*HDq];
__device__ float g_v     [(size_t)NTOK*KVHq*HDq];
__device__ float g_o     [(size_t)NTOK*Dq];
__device__ float g_x1    [(size_t)NTOK*Dq];
__device__ float g_h2    [(size_t)NTOK*Dq];
__device__ float g_hidden[(size_t)NSLOT*FFq];   // 128MB
__device__ float g_y     [(size_t)NSLOT*Dq];    // 32MB
__device__ float g_gate  [NSLOT];
__device__ int   g_lists [Eq*NTOK];
__device__ int   g_counts[Eq];

__device__ __forceinline__ float gelu_f(float x) {
    return 0.5f * x * (1.0f + erff(x * 0.70710678118654752f));
}

// ---------------- LayerNorm: one block per row ----------------
__global__ void ln_kernel(const float* __restrict__ in, const float* __restrict__ g,
                          const float* __restrict__ b, float* __restrict__ out) {
    int row = blockIdx.x; int t = threadIdx.x;
    __shared__ float red[256];
    const float* x = in + (size_t)row * Dq;
    float s = 0.f;
    for (int d = t; d < Dq; d += 256) s += x[d];
    red[t] = s; __syncthreads();
    for (int o = 128; o > 0; o >>= 1) { if (t < o) red[t] += red[t + o]; __syncthreads(); }
    float mean = red[0] * (1.0f / Dq);
    __syncthreads();
    float sq = 0.f;
    for (int d = t; d < Dq; d += 256) { float c = x[d] - mean; sq += c * c; }
    red[t] = sq; __syncthreads();
    for (int o = 128; o > 0; o >>= 1) { if (t < o) red[t] += red[t + o]; __syncthreads(); }
    float rstd = rsqrtf(red[0] * (1.0f / Dq) + 1e-5f);
    for (int d = t; d < Dq; d += 256)
        out[(size_t)row * Dq + d] = (x[d] - mean) * rstd * g[d] + b[d];
}

// ---------------- small generic GEMM: one block row, A row cached in smem ----
__global__ void gemm_row(const float* __restrict__ A, const float* __restrict__ Bm,
                         float* __restrict__ C, int N, int K) {
    __shared__ float sA[1024];
    int m = blockIdx.y;
    for (int k = threadIdx.x; k < K; k += blockDim.x) sA[k] = A[(size_t)m * K + k];
    __syncthreads();
    int n = blockIdx.x * blockDim.x + threadIdx.x;
    if (n >= N) return;
    float acc = 0.f;
    for (int k = 0; k < K; k++) acc += sA[k] * Bm[(size_t)k * N + n];
    C[(size_t)m * N + n] = acc;
}

// ---------------- RoPE (interleaved pairs) ----------------
__global__ void rope_kernel(float* buf, int nheads, int total) {
    int idx = blockIdx.x * blockDim.x + threadIdx.x;
    if (idx >= total) return;
    int i    = idx & 31;
    int rest = idx >> 5;
    int head = rest % nheads;
    int tok  = rest / nheads;
    int s    = tok % Sq;
    float inv = powf(10000.0f, -(float)(2 * i) / 64.0f);
    float fr  = (float)s * inv;
    float c = cosf(fr), sn = sinf(fr);
    size_t base = ((size_t)tok * nheads + head) * 64 + 2 * i;
    float x1 = buf[base], x2 = buf[base + 1];
    buf[base]     = x1 * c - x2 * sn;
    buf[base + 1] = x1 * sn + x2 * c;
}

// ---------------- split packed KV into K / V ----------------
__global__ void split_kv(const float* __restrict__ kvfull, float* __restrict__ k,
                         float* __restrict__ v) {
    int idx = blockIdx.x * blockDim.x + threadIdx.x;
    if (idx >= NTOK * KVHq * HDq) return;
    int hd = idx & 63; int rest = idx >> 6; int kvh = rest & 3; int tok = rest >> 2;
    size_t src = (size_t)tok * 512 + kvh * 128 + hd * 2;
    k[idx] = kvfull[src];
    v[idx] = kvfull[src + 1];
}

// ---------------- flash-style causal attention ----------------
// grid: (S/64, H, B), block: 64 threads, thread t owns query qt*64+t
__global__ __launch_bounds__(64) void flash_kernel(const float* __restrict__ q,
                                                   const float* __restrict__ kb,
                                                   const float* __restrict__ vb,
                                                   float* __restrict__ o) {
    int qt = blockIdx.x, h = blockIdx.y, b = blockIdx.z;
    int t = threadIdx.x;
    int qi = qt * 64 + t;
    __shared__ float sk[64][64];
    __shared__ float sv[64][64];
    __shared__ float ss[64][64];  // [j][t]
    float qreg[64];
    const float* qrow = q + (((size_t)b * Sq + qi) * Hq + h) * HDq;
#pragma unroll
    for (int d = 0; d < 64; d++) qreg[d] = qrow[d] * 0.125f;  // fold 1/sqrt(64)
    float acc[64];
#pragma unroll
    for (int d = 0; d < 64; d++) acc[d] = 0.f;
    float m = -1e30f, l = 0.f;
    int kvh = h >> 2;
    for (int kt = 0; kt <= qt; kt++) {
        const float* kbase = kb + (((size_t)b * Sq + kt * 64 + t) * KVHq + kvh) * HDq;
        const float* vbase = vb + (((size_t)b * Sq + kt * 64 + t) * KVHq + kvh) * HDq;
#pragma unroll 16
        for (int d = 0; d < 64; d += 4) {
            *(float4*)&sk[t][d] = *(const float4*)(kbase + d);
            *(float4*)&sv[t][d] = *(const float4*)(vbase + d);
        }
        __syncthreads();
        int jend = qi - kt * 64 + 1; if (jend > 64) jend = 64;
        float tmax = -1e30f;
        for (int j = 0; j < jend; j++) {
            float s = 0.f;
#pragma unroll
            for (int d = 0; d < 64; d += 4) {
                float4 kk = *(const float4*)&sk[j][d];
                s += qreg[d] * kk.x + qreg[d + 1] * kk.y + qreg[d + 2] * kk.z + qreg[d + 3] * kk.w;
            }
            ss[j][t] = s;
            tmax = fmaxf(tmax, s);
        }
        float mn = fmaxf(m, tmax);
        float corr = expf(m - mn);
        l *= corr;
#pragma unroll
        for (int d = 0; d < 64; d++) acc[d] *= corr;
        for (int j = 0; j < jend; j++) {
            float p = expf(ss[j][t] - mn);
            l += p;
#pragma unroll
            for (int d = 0; d < 64; d += 4) {
                float4 vv = *(const float4*)&sv[j][d];
                acc[d]     += p * vv.x;
                acc[d + 1] += p * vv.y;
                acc[d + 2] += p * vv.z;
                acc[d + 3] += p * vv.w;
            }
        }
        m = mn;
        __syncthreads();
    }
    float invl = 1.f / l;
    float* orow = o + (((size_t)b * Sq + qi) * Hq + h) * HDq;
#pragma unroll
    for (int d = 0; d < 64; d++) orow[d] = acc[d] * invl;
}

// ---------------- tiled SGEMM 64x64x16, fused residual+bias ----------------
// C = xres + A@W + bias ; M=4096, N=1024, K=1024
__global__ __launch_bounds__(256) void gemm_out(const float* __restrict__ A,
                                                const float* __restrict__ W,
                                                const float* __restrict__ xres,
                                                const float* __restrict__ bias,
                                                float* __restrict__ C) {
    const int Kn = 1024, Nn = 1024;
    __shared__ float As[16][68];
    __shared__ float Bs[16][64];
    int tid = threadIdx.x;
    int m0 = blockIdx.y * 64, n0 = blockIdx.x * 64;
    int am = tid >> 2, ak = (tid & 3) * 4;
    int bk = tid >> 4, bn = (tid & 15) * 4;
    int ty = tid >> 4, tx = tid & 15;
    float acc[4][4] = {};
    for (int k0 = 0; k0 < Kn; k0 += 16) {
        float4 av = *(const float4*)(A + (size_t)(m0 + am) * Kn + k0 + ak);
        float4 bv = *(const float4*)(W + (size_t)(k0 + bk) * Nn + n0 + bn);
        As[ak][am] = av.x; As[ak + 1][am] = av.y; As[ak + 2][am] = av.z; As[ak + 3][am] = av.w;
        *(float4*)&Bs[bk][bn] = bv;
        __syncthreads();
#pragma unroll
        for (int k = 0; k < 16; k++) {
            float4 a = *(const float4*)&As[k][ty * 4];
            float4 b = *(const float4*)&Bs[k][tx * 4];
            acc[0][0] += a.x * b.x; acc[0][1] += a.x * b.y; acc[0][2] += a.x * b.z; acc[0][3] += a.x * b.w;
            acc[1][0] += a.y * b.x; acc[1][1] += a.y * b.y; acc[1][2] += a.y * b.z; acc[1][3] += a.y * b.w;
            acc[2][0] += a.z * b.x; acc[2][1] += a.z * b.y; acc[2][2] += a.z * b.z; acc[2][3] += a.z * b.w;
            acc[3][0] += a.w * b.x; acc[3][1] += a.w * b.y; acc[3][2] += a.w * b.z; acc[3][3] += a.w * b.w;
        }
        __syncthreads();
    }
#pragma unroll
    for (int i = 0; i < 4; i++) {
        int mg = m0 + ty * 4 + i;
#pragma unroll
        for (int j = 0; j < 4; j++) {
            int ng = n0 + tx * 4 + j;
            C[(size_t)mg * Nn + ng] = xres[(size_t)mg * Nn + ng] + acc[i][j] + bias[ng];
        }
    }
}

// ---------------- zero expert counters ----------------
__global__ void zero_counts(int* c) { if (threadIdx.x < Eq) c[threadIdx.x] = 0; }

// ---------------- router: logits, top-2, gates, expert lists ----------------
__global__ void router_kernel(const float* __restrict__ h2, const float* __restrict__ rw,
                              float* __restrict__ logits, float* __restrict__ gate,
                              int* __restrict__ lists, int* __restrict__ counts) {
    int tok = blockIdx.x * blockDim.x + threadIdx.x;
    if (tok >= NTOK) return;
    float l[8];
#pragma unroll
    for (int e = 0; e < 8; e++) l[e] = 0.f;
    const float* hr = h2 + (size_t)tok * Dq;
    for (int k = 0; k < Dq; k++) {
        float hv = hr[k];
#pragma unroll
        for (int e = 0; e < 8; e++) l[e] += hv * rw[k * 8 + e];
    }
#pragma unroll
    for (int e = 0; e < 8; e++) logits[(size_t)tok * 8 + e] = l[e];
    int i0 = 0;
#pragma unroll
    for (int e = 1; e < 8; e++) if (l[e] > l[i0]) i0 = e;
    int i1 = -1;
#pragma unroll
    for (int e = 0; e < 8; e++) {
        if (e == i0) continue;
        if (i1 < 0 || l[e] > l[i1]) i1 = e;
    }
    float e1 = expf(l[i1] - l[i0]);
    float denom = 1.f / (1.f + e1);
    gate[tok * 2]     = denom;
    gate[tok * 2 + 1] = e1 * denom;
    int pos0 = atomicAdd(&counts[i0], 1);
    lists[i0 * NTOK + pos0] = tok * 2;
    int pos1 = atomicAdd(&counts[i1], 1);
    lists[i1 * NTOK + pos1] = tok * 2 + 1;
}

// ---------------- MoE GEMM1: hidden = gelu(h2 @ fc_w[e] + fc_b[e]) ----------
// grid (FF/64, NTOK/64, E) ; indirect A rows via expert lists
__global__ __launch_bounds__(256) void moe_gemm1(const float* __restrict__ Ah,
                                                 const float* __restrict__ fcw,
                                                 const float* __restrict__ fcb,
                                                 const int* __restrict__ lists,
                                                 const int* __restrict__ counts,
                                                 float* __restrict__ hid) {
    int e = blockIdx.z;
    int cnt = counts[e];
    int m0 = blockIdx.y * 64;
    if (m0 >= cnt) return;
    int n0 = blockIdx.x * 64;
    __shared__ float As[16][68];
    __shared__ float Bs[16][64];
    __shared__ int sp[64];
    int tid = threadIdx.x;
    if (tid < 64) { int r = m0 + tid; sp[tid] = (r < cnt) ? lists[e * NTOK + r] : -1; }
    __syncthreads();
    int am = tid >> 2, ak = (tid & 3) * 4;
    int bk = tid >> 4, bn = (tid & 15) * 4;
    int ty = tid >> 4, tx = tid & 15;
    int pa = sp[am];
    const float* arow = (pa >= 0) ? (Ah + (size_t)(pa >> 1) * Dq) : nullptr;
    const float* W = fcw + (size_t)e * Dq * FFq;
    float acc[4][4] = {};
    for (int k0 = 0; k0 < Dq; k0 += 16) {
        float4 av = arow ? *(const float4*)(arow + k0 + ak) : make_float4(0.f, 0.f, 0.f, 0.f);
        float4 bv = *(const float4*)(W + (size_t)(k0 + bk) * FFq + n0 + bn);
        As[ak][am] = av.x; As[ak + 1][am] = av.y; As[ak + 2][am] = av.z; As[ak + 3][am] = av.w;
        *(float4*)&Bs[bk][bn] = bv;
        __syncthreads();
#pragma unroll
        for (int k = 0; k < 16; k++) {
            float4 a = *(const float4*)&As[k][ty * 4];
            float4 b = *(const float4*)&Bs[k][tx * 4];
            acc[0][0] += a.x * b.x; acc[0][1] += a.x * b.y; acc[0][2] += a.x * b.z; acc[0][3] += a.x * b.w;
            acc[1][0] += a.y * b.x; acc[1][1] += a.y * b.y; acc[1][2] += a.y * b.z; acc[1][3] += a.y * b.w;
            acc[2][0] += a.z * b.x; acc[2][1] += a.z * b.y; acc[2][2] += a.z * b.z; acc[2][3] += a.z * b.w;
            acc[3][0] += a.w * b.x; acc[3][1] += a.w * b.y; acc[3][2] += a.w * b.z; acc[3][3] += a.w * b.w;
        }
        __syncthreads();
    }
#pragma unroll
    for (int i = 0; i < 4; i++) {
        int p = sp[ty * 4 + i];
        if (p < 0) continue;
        float* dst = hid + (size_t)p * FFq + n0 + tx * 4;
        const float* bb = fcb + (size_t)e * FFq + n0 + tx * 4;
#pragma unroll
        for (int j = 0; j < 4; j++) dst[j] = gelu_f(acc[i][j] + bb[j]);
    }
}

// ---------------- MoE GEMM2: y = gate * (hidden @ proj_w[e] + proj_b[e]) ----
// grid (D/64, NTOK/64, E)
__global__ __launch_bounds__(256) void moe_gemm2(const float* __restrict__ hid,
                                                 const float* __restrict__ pw,
                                                 const float* __restrict__ pb,
                                                 const int* __restrict__ lists,
                                                 const int* __restrict__ counts,
                                                 float* __restrict__ yb,
                                                 const float* __restrict__ gate) {
    int e = blockIdx.z;
    int cnt = counts[e];
    int m0 = blockIdx.y * 64;
    if (m0 >= cnt) return;
    int n0 = blockIdx.x * 64;
    __shared__ float As[16][68];
    __shared__ float Bs[16][64];
    __shared__ int sp[64];
    int tid = threadIdx.x;
    if (tid < 64) { int r = m0 + tid; sp[tid] = (r < cnt) ? lists[e * NTOK + r] : -1; }
    __syncthreads();
    int am = tid >> 2, ak = (tid & 3) * 4;
    int bk = tid >> 4, bn = (tid & 15) * 4;
    int ty = tid >> 4, tx = tid & 15;
    int pa = sp[am];
    const float* arow = (pa >= 0) ? (hid + (size_t)pa * FFq) : nullptr;
    const float* W = pw + (size_t)e * FFq * Dq;
    float acc[4][4] = {};
    for (int k0 = 0; k0 < FFq; k0 += 16) {
        float4 av = arow ? *(const float4*)(arow + k0 + ak) : make_float4(0.f, 0.f, 0.f, 0.f);
        float4 bv = *(const float4*)(W + (size_t)(k0 + bk) * Dq + n0 + bn);
        As[ak][am] = av.x; As[ak + 1][am] = av.y; As[ak + 2][am] = av.z; As[ak + 3][am] = av.w;
        *(float4*)&Bs[bk][bn] = bv;
        __syncthreads();
#pragma unroll
        for (int k = 0; k < 16; k++) {
            float4 a = *(const float4*)&As[k][ty * 4];
            float4 b = *(const float4*)&Bs[k][tx * 4];
            acc[0][0] += a.x * b.x; acc[0][1] += a.x * b.y; acc[0][2] += a.x * b.z; acc[0][3] += a.x * b.w;
            acc[1][0] += a.y * b.x; acc[1][1] += a.y * b.y; acc[1][2] += a.y * b.z; acc[1][3] += a.y * b.w;
            acc[2][0] += a.z * b.x; acc[2][1] += a.z * b.y; acc[2][2] += a.z * b.z; acc[2][3] += a.z * b.w;
            acc[3][0] += a.w * b.x; acc[3][1] += a.w * b.y; acc[3][2] += a.w * b.z; acc[3][3] += a.w * b.w;
        }
        __syncthreads();
    }
#pragma unroll
    for (int i = 0; i < 4; i++) {
        int p = sp[ty * 4 + i];
        if (p < 0) continue;
        float gv = gate[p];
        float* dst = yb + (size_t)p * Dq + n0 + tx * 4;
        const float* bb = pb + (size_t)e * Dq + n0 + tx * 4;
#pragma unroll
        for (int j = 0; j < 4; j++) dst[j] = gv * (acc[i][j] + bb[j]);
    }
}

// ---------------- finalize: out = x1 + LN(y_slot0 + y_slot1) ----------------
__global__ void finalize_kernel(const float* __restrict__ x1, const float* __restrict__ yb,
                                const float* __restrict__ g, const float* __restrict__ b,
                                float* __restrict__ out) {
    int row = blockIdx.x; int t = threadIdx.x;
    __shared__ float sv[1024];
    __shared__ float red[256];
    float s = 0.f;
    for (int d = t; d < Dq; d += 256) {
        float v = yb[(size_t)(row * 2) * Dq + d] + yb[(size_t)(row * 2 + 1) * Dq + d];
        sv[d] = v;
        s += v;
    }
    red[t] = s; __syncthreads();
    for (int o = 128; o > 0; o >>= 1) { if (t < o) red[t] += red[t + o]; __syncthreads(); }
    float mean = red[0] * (1.0f / Dq);
    __syncthreads();
    float sq = 0.f;
    for (int d = t; d < Dq; d += 256) { float c = sv[d] - mean; sq += c * c; }
    red[t] = sq; __syncthreads();
    for (int o = 128; o > 0; o >>= 1) { if (t < o) red[t] += red[t + o]; __syncthreads(); }
    float rstd = rsqrtf(red[0] * (1.0f / Dq) + 1e-5f);
    for (int d = t; d < Dq; d += 256)
        out[(size_t)row * Dq + d] = x1[(size_t)row * Dq + d] + (sv[d] - mean) * rstd * g[d] + b[d];
}

// ---------------- launch ----------------
extern "C" void kernel_launch(void* const* d_in, const int* in_sizes, int n_in,
                              void* d_out, int out_size) {
    const float* x    = (const float*)d_in[0];
    const float* ln1g = (const float*)d_in[1];
    const float* ln1b = (const float*)d_in[2];
    const float* qaw  = (const float*)d_in[3];
    const float* qbw  = (const float*)d_in[4];
    const float* kvaw = (const float*)d_in[5];
    const float* kvbw = (const float*)d_in[6];
    const float* outw = (const float*)d_in[7];
    const float* outb = (const float*)d_in[8];
    const float* ln2g = (const float*)d_in[9];
    const float* ln2b = (const float*)d_in[10];
    const float* rw   = (const float*)d_in[11];
    const float* fcw  = (const float*)d_in[12];
    const float* fcb  = (const float*)d_in[13];
    const float* pw   = (const float*)d_in[14];
    const float* pb   = (const float*)d_in[15];
    const float* mlng = (const float*)d_in[16];
    const float* mlnb = (const float*)d_in[17];

    float* out1 = (float*)d_out;
    float* out2 = out1 + (size_t)NTOK * Dq;

    float *h, *qlat, *q, *kvlat, *kvfull, *kb, *vb, *ob, *x1, *h2, *hid, *yb, *gate;
    int *lists, *counts;
    cudaGetSymbolAddress((void**)&h, g_h);
    cudaGetSymbolAddress((void**)&qlat, g_qlat);
    cudaGetSymbolAddress((void**)&q, g_q);
    cudaGetSymbolAddress((void**)&kvlat, g_kvlat);
    cudaGetSymbolAddress((void**)&kvfull, g_kvfull);
    cudaGetSymbolAddress((void**)&kb, g_k);
    cudaGetSymbolAddress((void**)&vb, g_v);
    cudaGetSymbolAddress((void**)&ob, g_o);
    cudaGetSymbolAddress((void**)&x1, g_x1);
    cudaGetSymbolAddress((void**)&h2, g_h2);
    cudaGetSymbolAddress((void**)&hid, g_hidden);
    cudaGetSymbolAddress((void**)&yb, g_y);
    cudaGetSymbolAddress((void**)&gate, g_gate);
    cudaGetSymbolAddress((void**)&lists, g_lists);
    cudaGetSymbolAddress((void**)&counts, g_counts);

    // 1. LN1
    ln_kernel<<<NTOK, 256>>>(x, ln1g, ln1b, h);
    // 2. q = (h @ q_a) @ q_b
    gemm_row<<<dim3(1, NTOK), 64>>>(h, qaw, qlat, QLATq, Dq);
    gemm_row<<<dim3(4, NTOK), 256>>>(qlat, qbw, q, Dq, QLATq);
    // 3. kv = (h @ kv_a) @ kv_b
    gemm_row<<<dim3(1, NTOK), 32>>>(h, kvaw, kvlat, KVLATq, Dq);
    gemm_row<<<dim3(2, NTOK), 256>>>(kvlat, kvbw, kvfull, 512, KVLATq);
    // 4. RoPE q, split kv, RoPE k
    rope_kernel<<<(NTOK * Hq * 32 + 255) / 256, 256>>>(q, Hq, NTOK * Hq * 32);
    split_kv<<<(NTOK * KVHq * HDq + 255) / 256, 256>>>(kvfull, kb, vb);
    rope_kernel<<<(NTOK * KVHq * 32 + 255) / 256, 256>>>(kb, KVHq, NTOK * KVHq * 32);
    // 5. attention
    flash_kernel<<<dim3(Sq / 64, Hq, Bq), 64>>>(q, kb, vb, ob);
    // 6. out proj + residual
    gemm_out<<<dim3(Dq / 64, NTOK / 64), 256>>>(ob, outw, x, outb, x1);
    // 7. LN2
    ln_kernel<<<NTOK, 256>>>(x1, ln2g, ln2b, h2);
    // 8. router
    zero_counts<<<1, 32>>>(counts);
    router_kernel<<<NTOK / 256, 256>>>(h2, rw, out2, gate, lists, counts);
    // 9. MoE
    moe_gemm1<<<dim3(FFq / 64, NTOK / 64, Eq), 256>>>(h2, fcw, fcb, lists, counts, hid);
    moe_gemm2<<<dim3(Dq / 64, NTOK / 64, Eq), 256>>>(hid, pw, pb, lists, counts, yb, gate);
    // 10. finalize
    finalize_kernel<<<NTOK, 256>>>(x1, yb, mlng, mlnb, out1);
}

// round 2
// speedup vs baseline: 1.0724x; 1.0724x over previous
#include <cuda_runtime.h>
#include <math.h>

#define Bq    2
#define Sq    2048
#define Dq    1024
#define Hq    16
#define KVHq  4
#define HDq   64
#define QLATq 64
#define KVLATq 32
#define Eq    8
#define FFq   4096
#define NTOK  (Bq*Sq)      // 4096
#define NSLOT (NTOK*2)     // 8192

typedef unsigned long long ull;

// ---------------- packed f32x2 helpers (sm_103a FFMA2 path) ----------------
__device__ __forceinline__ ull pack2(float lo, float hi) {
    ull r; asm("mov.b64 %0,{%1,%2};" : "=l"(r) : "f"(lo), "f"(hi)); return r;
}
__device__ __forceinline__ void unpack2(ull v, float& lo, float& hi) {
    asm("mov.b64 {%0,%1},%2;" : "=f"(lo), "=f"(hi) : "l"(v));
}
__device__ __forceinline__ void fma2(ull& d, ull a, ull b) {
    asm("fma.rn.f32x2 %0,%1,%2,%0;" : "+l"(d) : "l"(a), "l"(b));
}
__device__ __forceinline__ void mul2(ull& d, ull a) {
    asm("mul.rn.f32x2 %0,%0,%1;" : "+l"(d) : "l"(a));
}

// ---------------- scratch (device globals; no allocations) ----------------
__device__ float g_h     [(size_t)NTOK*Dq];
__device__ float g_qlat  [(size_t)NTOK*QLATq];
__device__ float g_q     [(size_t)NTOK*Dq];
__device__ float g_kvlat [(size_t)NTOK*KVLATq];
__device__ float g_kvfull[(size_t)NTOK*512];
__device__ float g_k     [(size_t)NTOK*KVHq*HDq];
__device__ float g_v     [(size_t)NTOK*KVHq*HDq];
__device__ float g_o     [(size_t)NTOK*Dq];
__device__ float g_x1    [(size_t)NTOK*Dq];
__device__ float g_h2    [(size_t)NTOK*Dq];
__device__ float g_hidden[(size_t)NSLOT*FFq];
__device__ float g_y     [(size_t)NSLOT*Dq];
__device__ float g_gate  [NSLOT];
__device__ int   g_lists [Eq*NTOK];
__device__ int   g_counts[Eq];

__device__ __forceinline__ float gelu_f(float x) {
    return 0.5f * x * (1.0f + erff(x * 0.70710678118654752f));
}

// ---------------- LayerNorm ----------------
__global__ void ln_kernel(const float* __restrict__ in, const float* __restrict__ g,
                          const float* __restrict__ b, float* __restrict__ out) {
    int row = blockIdx.x; int t = threadIdx.x;
    __shared__ float red[256];
    const float* x = in + (size_t)row * Dq;
    float s = 0.f;
    for (int d = t; d < Dq; d += 256) s += x[d];
    red[t] = s; __syncthreads();
    for (int o = 128; o > 0; o >>= 1) { if (t < o) red[t] += red[t + o]; __syncthreads(); }
    float mean = red[0] * (1.0f / Dq);
    __syncthreads();
    float sq = 0.f;
    for (int d = t; d < Dq; d += 256) { float c = x[d] - mean; sq += c * c; }
    red[t] = sq; __syncthreads();
    for (int o = 128; o > 0; o >>= 1) { if (t < o) red[t] += red[t + o]; __syncthreads(); }
    float rstd = rsqrtf(red[0] * (1.0f / Dq) + 1e-5f);
    for (int d = t; d < Dq; d += 256)
        out[(size_t)row * Dq + d] = (x[d] - mean) * rstd * g[d] + b[d];
}

// ---------------- 64x64x16 tiled GEMM (small N cases, guarded) ----------------
__global__ __launch_bounds__(256) void gemm64(const float* __restrict__ A,
                                              const float* __restrict__ Bm,
                                              float* __restrict__ C,
                                              int N, int K) {
    __shared__ float As[16][68];
    __shared__ float Bs[16][64];
    int tid = threadIdx.x;
    int m0 = blockIdx.y * 64, n0 = blockIdx.x * 64;
    int am = tid >> 2, ak = (tid & 3) * 4;
    int bk = tid >> 4, bn = (tid & 15) * 4;
    int ty = tid >> 4, tx = tid & 15;
    float acc[4][4] = {};
    for (int k0 = 0; k0 < K; k0 += 16) {
        float4 av = *(const float4*)(A + (size_t)(m0 + am) * K + k0 + ak);
        float4 bv = make_float4(0.f, 0.f, 0.f, 0.f);
        if (n0 + bn + 4 <= N) bv = *(const float4*)(Bm + (size_t)(k0 + bk) * N + n0 + bn);
        As[ak][am] = av.x; As[ak + 1][am] = av.y; As[ak + 2][am] = av.z; As[ak + 3][am] = av.w;
        *(float4*)&Bs[bk][bn] = bv;
        __syncthreads();
#pragma unroll
        for (int k = 0; k < 16; k++) {
            float4 a = *(const float4*)&As[k][ty * 4];
            float4 b = *(const float4*)&Bs[k][tx * 4];
            acc[0][0] += a.x * b.x; acc[0][1] += a.x * b.y; acc[0][2] += a.x * b.z; acc[0][3] += a.x * b.w;
            acc[1][0] += a.y * b.x; acc[1][1] += a.y * b.y; acc[1][2] += a.y * b.z; acc[1][3] += a.y * b.w;
            acc[2][0] += a.z * b.x; acc[2][1] += a.z * b.y; acc[2][2] += a.z * b.z; acc[2][3] += a.z * b.w;
            acc[3][0] += a.w * b.x; acc[3][1] += a.w * b.y; acc[3][2] += a.w * b.z; acc[3][3] += a.w * b.w;
        }
        __syncthreads();
    }
#pragma unroll
    for (int i = 0; i < 4; i++) {
        int mg = m0 + ty * 4 + i;
#pragma unroll
        for (int j = 0; j < 4; j++) {
            int ng = n0 + tx * 4 + j;
            if (ng < N) C[(size_t)mg * N + ng] = acc[i][j];
        }
    }
}

// ---------------- 128x128x8 double-buffered SGEMM with f32x2 core ----------
// MODE 0: C = A@B                         (plain)
// MODE 1: C = extra + A@B + bias          (out-proj + residual)
// MODE 2: gathered rows (p>>1), C[p] = gelu(A@B + bias_e)   (MoE fc)
// MODE 3: gathered rows p,     C[p] = extra[p]*(A@B + bias_e) (MoE proj)
template<int MODE>
__global__ __launch_bounds__(256) void gemm128(
    const float* __restrict__ A, const float* __restrict__ Bm, float* __restrict__ C,
    int N, int K,
    const float* __restrict__ bias, const float* __restrict__ extra,
    const int* __restrict__ lists, const int* __restrict__ counts)
{
    __shared__ __align__(16) float As[2][8][128];
    __shared__ __align__(16) float Bs[2][8][128];
    __shared__ int sp[128];
    int tid = threadIdx.x;
    int n0 = blockIdx.x * 128;
    int m0 = blockIdx.y * 128;
    const float* Bb = Bm;
    const float* biasb = bias;
    if (MODE >= 2) {
        int e = blockIdx.z;
        int cnt = counts[e];
        if (m0 >= cnt) return;
        if (tid < 128) { int r = m0 + tid; sp[tid] = (r < cnt) ? lists[e * NTOK + r] : -1; }
        Bb = Bm + (size_t)e * K * N;
        biasb = bias + (size_t)e * N;
        __syncthreads();
    }
    int ar = tid >> 1, ac = (tid & 1) * 4;
    int bk = tid >> 5, bn = (tid & 31) * 4;
    const float* arow;
    if (MODE == 2) { int p = sp[ar]; arow = (p >= 0) ? A + (size_t)(p >> 1) * K : nullptr; }
    else if (MODE == 3) { int p = sp[ar]; arow = (p >= 0) ? A + (size_t)p * K : nullptr; }
    else arow = A + (size_t)(m0 + ar) * K;

    float4 av = arow ? *(const float4*)(arow + ac) : make_float4(0.f, 0.f, 0.f, 0.f);
    float4 bv = *(const float4*)(Bb + (size_t)bk * N + n0 + bn);
    As[0][ac][ar] = av.x; As[0][ac + 1][ar] = av.y; As[0][ac + 2][ar] = av.z; As[0][ac + 3][ar] = av.w;
    *(float4*)&Bs[0][bk][bn] = bv;
    __syncthreads();

    int ty = tid >> 4, tx = tid & 15;
    ull acc2[8][4];
#pragma unroll
    for (int i = 0; i < 8; i++)
#pragma unroll
        for (int j = 0; j < 4; j++) acc2[i][j] = 0ull;

    int KT = K >> 3;
    int buf = 0;
    for (int kt = 0; kt < KT; kt++) {
        if (kt + 1 < KT) {
            int k0 = (kt + 1) << 3;
            av = arow ? *(const float4*)(arow + k0 + ac) : make_float4(0.f, 0.f, 0.f, 0.f);
            bv = *(const float4*)(Bb + (size_t)(k0 + bk) * N + n0 + bn);
        }
#pragma unroll
        for (int k = 0; k < 8; k++) {
            float4 a0 = *(const float4*)&As[buf][k][ty * 8];
            float4 a1 = *(const float4*)&As[buf][k][ty * 8 + 4];
            longlong2 bl0 = *(const longlong2*)&Bs[buf][k][tx * 8];
            longlong2 bl1 = *(const longlong2*)&Bs[buf][k][tx * 8 + 4];
            ull b2[4] = { (ull)bl0.x, (ull)bl0.y, (ull)bl1.x, (ull)bl1.y };
            float a[8] = { a0.x, a0.y, a0.z, a0.w, a1.x, a1.y, a1.z, a1.w };
#pragma unroll
            for (int i = 0; i < 8; i++) {
                ull aa = pack2(a[i], a[i]);
#pragma unroll
                for (int j = 0; j < 4; j++) fma2(acc2[i][j], aa, b2[j]);
            }
        }
        if (kt + 1 < KT) {
            buf ^= 1;
            As[buf][ac][ar] = av.x; As[buf][ac + 1][ar] = av.y;
            As[buf][ac + 2][ar] = av.z; As[buf][ac + 3][ar] = av.w;
            *(float4*)&Bs[buf][bk][bn] = bv;
        }
        __syncthreads();
    }

#pragma unroll
    for (int i = 0; i < 8; i++) {
        int mi = ty * 8 + i;
        float accf[8];
#pragma unroll
        for (int j = 0; j < 4; j++) unpack2(acc2[i][j], accf[2 * j], accf[2 * j + 1]);
        if (MODE <= 1) {
            size_t row = (size_t)(m0 + mi) * N;
#pragma unroll
            for (int j = 0; j < 8; j += 4) {
                int ng = n0 + tx * 8 + j;
                float4 r;
                r.x = accf[j]; r.y = accf[j + 1]; r.z = accf[j + 2]; r.w = accf[j + 3];
                if (MODE == 1) {
                    const float4 xr = *(const float4*)(extra + row + ng);
                    r.x += xr.x + bias[ng]; r.y += xr.y + bias[ng + 1];
                    r.z += xr.z + bias[ng + 2]; r.w += xr.w + bias[ng + 3];
                }
                *(float4*)(C + row + ng) = r;
            }
        } else {
            int p = sp[mi];
            if (p < 0) continue;
            float* dst = C + (size_t)p * N;
            int ng = n0 + tx * 8;
            if (MODE == 2) {
#pragma unroll
                for (int j = 0; j < 8; j++) dst[ng + j] = gelu_f(accf[j] + biasb[ng + j]);
            } else {
                float gv = extra[p];
#pragma unroll
                for (int j = 0; j < 8; j++) dst[ng + j] = gv * (accf[j] + biasb[ng + j]);
            }
        }
    }
}

// ---------------- RoPE ----------------
__global__ void rope_kernel(float* buf, int nheads, int total) {
    int idx = blockIdx.x * blockDim.x + threadIdx.x;
    if (idx >= total) return;
    int i    = idx & 31;
    int rest = idx >> 5;
    int head = rest % nheads;
    int tok  = rest / nheads;
    int s    = tok % Sq;
    float inv = powf(10000.0f, -(float)(2 * i) / 64.0f);
    float fr  = (float)s * inv;
    float c = cosf(fr), sn = sinf(fr);
    size_t base = ((size_t)tok * nheads + head) * 64 + 2 * i;
    float x1 = buf[base], x2 = buf[base + 1];
    buf[base]     = x1 * c - x2 * sn;
    buf[base + 1] = x1 * sn + x2 * c;
}

// ---------------- split packed KV ----------------
__global__ void split_kv(const float* __restrict__ kvfull, float* __restrict__ k,
                         float* __restrict__ v) {
    int idx = blockIdx.x * blockDim.x + threadIdx.x;
    if (idx >= NTOK * KVHq * HDq) return;
    int hd = idx & 63; int rest = idx >> 6; int kvh = rest & 3; int tok = rest >> 2;
    size_t src = (size_t)tok * 512 + kvh * 128 + hd * 2;
    k[idx] = kvfull[src];
    v[idx] = kvfull[src + 1];
}

// ---------------- flash attention with f32x2 core ----------------
__global__ __launch_bounds__(64) void flash_kernel(const float* __restrict__ q,
                                                   const float* __restrict__ kb,
                                                   const float* __restrict__ vb,
                                                   float* __restrict__ o) {
    int qt = blockIdx.x, h = blockIdx.y, b = blockIdx.z;
    int t = threadIdx.x;
    int qi = qt * 64 + t;
    __shared__ __align__(16) float sk[64][64];
    __shared__ __align__(16) float sv[64][64];
    __shared__ float ss[64][64];
    ull q2[32];
    const float* qrow = q + (((size_t)b * Sq + qi) * Hq + h) * HDq;
#pragma unroll
    for (int d = 0; d < 64; d += 2) q2[d >> 1] = pack2(qrow[d] * 0.125f, qrow[d + 1] * 0.125f);
    ull acc2[32];
#pragma unroll
    for (int d = 0; d < 32; d++) acc2[d] = 0ull;
    float m = -1e30f, l = 0.f;
    int kvh = h >> 2;
    for (int kt = 0; kt <= qt; kt++) {
        const float* kbase = kb + (((size_t)b * Sq + kt * 64 + t) * KVHq + kvh) * HDq;
        const float* vbase = vb + (((size_t)b * Sq + kt * 64 + t) * KVHq + kvh) * HDq;
#pragma unroll 16
        for (int d = 0; d < 64; d += 4) {
            *(float4*)&sk[t][d] = *(const float4*)(kbase + d);
            *(float4*)&sv[t][d] = *(const float4*)(vbase + d);
        }
        __syncthreads();
        int jend = qi - kt * 64 + 1; if (jend > 64) jend = 64;
        float tmax = -1e30f;
        for (int j = 0; j < jend; j++) {
            const longlong2* k2 = (const longlong2*)&sk[j][0];
            ull s0 = 0ull, s1 = 0ull, s2 = 0ull, s3 = 0ull;
#pragma unroll
            for (int d = 0; d < 8; d++) {
                longlong2 ka = k2[2 * d], kb2 = k2[2 * d + 1];
                fma2(s0, q2[4 * d],     (ull)ka.x);
                fma2(s1, q2[4 * d + 1], (ull)ka.y);
                fma2(s2, q2[4 * d + 2], (ull)kb2.x);
                fma2(s3, q2[4 * d + 3], (ull)kb2.y);
            }
            float a0, a1, b0, b1, c0, c1, d0, d1;
            unpack2(s0, a0, a1); unpack2(s1, b0, b1);
            unpack2(s2, c0, c1); unpack2(s3, d0, d1);
            float s = ((a0 + a1) + (b0 + b1)) + ((c0 + c1) + (d0 + d1));
            ss[j][t] = s;
            tmax = fmaxf(tmax, s);
        }
        float mn = fmaxf(m, tmax);
        float corr = expf(m - mn);
        l *= corr;
        ull corr2 = pack2(corr, corr);
#pragma unroll
        for (int d = 0; d < 32; d++) mul2(acc2[d], corr2);
        for (int j = 0; j < jend; j++) {
            float p = expf(ss[j][t] - mn);
            l += p;
            ull p2 = pack2(p, p);
            const longlong2* v2 = (const longlong2*)&sv[j][0];
#pragma unroll
            for (int d = 0; d < 16; d++) {
                longlong2 vv = v2[d];
                fma2(acc2[2 * d],     p2, (ull)vv.x);
                fma2(acc2[2 * d + 1], p2, (ull)vv.y);
            }
        }
        m = mn;
        __syncthreads();
    }
    float invl = 1.f / l;
    float* orow = o + (((size_t)b * Sq + qi) * Hq + h) * HDq;
#pragma unroll
    for (int d = 0; d < 32; d++) {
        float lo, hi; unpack2(acc2[d], lo, hi);
        orow[2 * d] = lo * invl;
        orow[2 * d + 1] = hi * invl;
    }
}

// ---------------- zero expert counters ----------------
__global__ void zero_counts(int* c) { if (threadIdx.x < Eq) c[threadIdx.x] = 0; }

// ---------------- router ----------------
__global__ void router_kernel(const float* __restrict__ h2, const float* __restrict__ rw,
                              float* __restrict__ logits, float* __restrict__ gate,
                              int* __restrict__ lists, int* __restrict__ counts) {
    int tok = blockIdx.x * blockDim.x + threadIdx.x;
    if (tok >= NTOK) return;
    float l[8];
#pragma unroll
    for (int e = 0; e < 8; e++) l[e] = 0.f;
    const float* hr = h2 + (size_t)tok * Dq;
    for (int k = 0; k < Dq; k++) {
        float hv = hr[k];
#pragma unroll
        for (int e = 0; e < 8; e++) l[e] += hv * rw[k * 8 + e];
    }
#pragma unroll
    for (int e = 0; e < 8; e++) logits[(size_t)tok * 8 + e] = l[e];
    int i0 = 0;
#pragma unroll
    for (int e = 1; e < 8; e++) if (l[e] > l[i0]) i0 = e;
    int i1 = -1;
#pragma unroll
    for (int e = 0; e < 8; e++) {
        if (e == i0) continue;
        if (i1 < 0 || l[e] > l[i1]) i1 = e;
    }
    float e1 = expf(l[i1] - l[i0]);
    float denom = 1.f / (1.f + e1);
    gate[tok * 2]     = denom;
    gate[tok * 2 + 1] = e1 * denom;
    int pos0 = atomicAdd(&counts[i0], 1);
    lists[i0 * NTOK + pos0] = tok * 2;
    int pos1 = atomicAdd(&counts[i1], 1);
    lists[i1 * NTOK + pos1] = tok * 2 + 1;
}

// ---------------- finalize ----------------
__global__ void finalize_kernel(const float* __restrict__ x1, const float* __restrict__ yb,
                                const float* __restrict__ g, const float* __restrict__ b,
                                float* __restrict__ out) {
    int row = blockIdx.x; int t = threadIdx.x;
    __shared__ float sv[1024];
    __shared__ float red[256];
    float s = 0.f;
    for (int d = t; d < Dq; d += 256) {
        float v = yb[(size_t)(row * 2) * Dq + d] + yb[(size_t)(row * 2 + 1) * Dq + d];
        sv[d] = v;
        s += v;
    }
    red[t] = s; __syncthreads();
    for (int o = 128; o > 0; o >>= 1) { if (t < o) red[t] += red[t + o]; __syncthreads(); }
    float mean = red[0] * (1.0f / Dq);
    __syncthreads();
    float sq = 0.f;
    for (int d = t; d < Dq; d += 256) { float c = sv[d] - mean; sq += c * c; }
    red[t] = sq; __syncthreads();
    for (int o = 128; o > 0; o >>= 1) { if (t < o) red[t] += red[t + o]; __syncthreads(); }
    float rstd = rsqrtf(red[0] * (1.0f / Dq) + 1e-5f);
    for (int d = t; d < Dq; d += 256)
        out[(size_t)row * Dq + d] = x1[(size_t)row * Dq + d] + (sv[d] - mean) * rstd * g[d] + b[d];
}

// ---------------- launch ----------------
extern "C" void kernel_launch(void* const* d_in, const int* in_sizes, int n_in,
                              void* d_out, int out_size) {
    const float* x    = (const float*)d_in[0];
    const float* ln1g = (const float*)d_in[1];
    const float* ln1b = (const float*)d_in[2];
    const float* qaw  = (const float*)d_in[3];
    const float* qbw  = (const float*)d_in[4];
    const float* kvaw = (const float*)d_in[5];
    const float* kvbw = (const float*)d_in[6];
    const float* outw = (const float*)d_in[7];
    const float* outb = (const float*)d_in[8];
    const float* ln2g = (const float*)d_in[9];
    const float* ln2b = (const float*)d_in[10];
    const float* rw   = (const float*)d_in[11];
    const float* fcw  = (const float*)d_in[12];
    const float* fcb  = (const float*)d_in[13];
    const float* pw   = (const float*)d_in[14];
    const float* pb   = (const float*)d_in[15];
    const float* mlng = (const float*)d_in[16];
    const float* mlnb = (const float*)d_in[17];

    float* out1 = (float*)d_out;
    float* out2 = out1 + (size_t)NTOK * Dq;

    float *h, *qlat, *q, *kvlat, *kvfull, *kb, *vb, *ob, *x1, *h2, *hid, *yb, *gate;
    int *lists, *counts;
    cudaGetSymbolAddress((void**)&h, g_h);
    cudaGetSymbolAddress((void**)&qlat, g_qlat);
    cudaGetSymbolAddress((void**)&q, g_q);
    cudaGetSymbolAddress((void**)&kvlat, g_kvlat);
    cudaGetSymbolAddress((void**)&kvfull, g_kvfull);
    cudaGetSymbolAddress((void**)&kb, g_k);
    cudaGetSymbolAddress((void**)&vb, g_v);
    cudaGetSymbolAddress((void**)&ob, g_o);
    cudaGetSymbolAddress((void**)&x1, g_x1);
    cudaGetSymbolAddress((void**)&h2, g_h2);
    cudaGetSymbolAddress((void**)&hid, g_hidden);
    cudaGetSymbolAddress((void**)&yb, g_y);
    cudaGetSymbolAddress((void**)&gate, g_gate);
    cudaGetSymbolAddress((void**)&lists, g_lists);
    cudaGetSymbolAddress((void**)&counts, g_counts);

    // 1. LN1
    ln_kernel<<<NTOK, 256>>>(x, ln1g, ln1b, h);
    // 2. q = (h @ q_a) @ q_b
    gemm64<<<dim3(1, NTOK / 64), 256>>>(h, qaw, qlat, QLATq, Dq);
    gemm128<0><<<dim3(Dq / 128, NTOK / 128), 256>>>(qlat, qbw, q, Dq, QLATq,
                                                    nullptr, nullptr, nullptr, nullptr);
    // 3. kv = (h @ kv_a) @ kv_b
    gemm64<<<dim3(1, NTOK / 64), 256>>>(h, kvaw, kvlat, KVLATq, Dq);
    gemm64<<<dim3(8, NTOK / 64), 256>>>(kvlat, kvbw, kvfull, 512, KVLATq);
    // 4. RoPE q, split kv, RoPE k
    rope_kernel<<<(NTOK * Hq * 32 + 255) / 256, 256>>>(q, Hq, NTOK * Hq * 32);
    split_kv<<<(NTOK * KVHq * HDq + 255) / 256, 256>>>(kvfull, kb, vb);
    rope_kernel<<<(NTOK * KVHq * 32 + 255) / 256, 256>>>(kb, KVHq, NTOK * KVHq * 32);
    // 5. attention
    flash_kernel<<<dim3(Sq / 64, Hq, Bq), 64>>>(q, kb, vb, ob);
    // 6. out proj + residual
    gemm128<1><<<dim3(Dq / 128, NTOK / 128), 256>>>(ob, outw, x1, Dq, Dq,
                                                    outb, x, nullptr, nullptr);
    // 7. LN2
    ln_kernel<<<NTOK, 256>>>(x1, ln2g, ln2b, h2);
    // 8. router
    zero_counts<<<1, 32>>>(counts);
    router_kernel<<<NTOK / 256, 256>>>(h2, rw, out2, gate, lists, counts);
    // 9. MoE
    gemm128<2><<<dim3(FFq / 128, NTOK / 128, Eq), 256>>>(h2, fcw, hid, FFq, Dq,
                                                         fcb, nullptr, lists, counts);
    gemm128<3><<<dim3(Dq / 128, NTOK / 128, Eq), 256>>>(hid, pw, yb, Dq, FFq,
                                                        pb, gate, lists, counts);
    // 10. finalize
    finalize_kernel<<<NTOK, 256>>>(x1, yb, mlng, mlnb, out1);
}

// round 3
// speedup vs baseline: 1.0759x; 1.0033x over previous
#include <cuda_runtime.h>
#include <math.h>

#define Bq    2
#define Sq    2048
#define Dq    1024
#define Hq    16
#define KVHq  4
#define HDq   64
#define QLATq 64
#define KVLATq 32
#define Eq    8
#define FFq   4096
#define NTOK  (Bq*Sq)      // 4096
#define NSLOT (NTOK*2)     // 8192

typedef unsigned long long ull;

// ---------------- packed f32x2 helpers (sm_103a FFMA2 path) ----------------
__device__ __forceinline__ ull pack2(float lo, float hi) {
    ull r; asm("mov.b64 %0,{%1,%2};" : "=l"(r) : "f"(lo), "f"(hi)); return r;
}
__device__ __forceinline__ void unpack2(ull v, float& lo, float& hi) {
    asm("mov.b64 {%0,%1},%2;" : "=f"(lo), "=f"(hi) : "l"(v));
}
__device__ __forceinline__ void fma2(ull& d, ull a, ull b) {
    asm("fma.rn.f32x2 %0,%1,%2,%0;" : "+l"(d) : "l"(a), "l"(b));
}
__device__ __forceinline__ void mul2(ull& d, ull a) {
    asm("mul.rn.f32x2 %0,%0,%1;" : "+l"(d) : "l"(a));
}

// ---------------- scratch (device globals; no allocations) ----------------
__device__ float g_h     [(size_t)NTOK*Dq];
__device__ float g_qlat  [(size_t)NTOK*QLATq];
__device__ float g_q     [(size_t)NTOK*Dq];
__device__ float g_kvlat [(size_t)NTOK*KVLATq];
__device__ float g_kvfull[(size_t)NTOK*512];
__device__ float g_k     [(size_t)NTOK*KVHq*HDq];
__device__ float g_v     [(size_t)NTOK*KVHq*HDq];
__device__ float g_o     [(size_t)NTOK*Dq];
__device__ float g_x1    [(size_t)NTOK*Dq];
__device__ float g_h2    [(size_t)NTOK*Dq];
__device__ float g_hidden[(size_t)NSLOT*FFq];
__device__ float g_y     [(size_t)NSLOT*Dq];
__device__ float g_gate  [NSLOT];
__device__ int   g_lists [Eq*NTOK];
__device__ int   g_counts[Eq];

__device__ __forceinline__ float gelu_f(float x) {
    return 0.5f * x * (1.0f + erff(x * 0.70710678118654752f));
}

// ---------------- LayerNorm ----------------
__global__ void ln_kernel(const float* __restrict__ in, const float* __restrict__ g,
                          const float* __restrict__ b, float* __restrict__ out) {
    int row = blockIdx.x; int t = threadIdx.x;
    __shared__ float red[256];
    const float* x = in + (size_t)row * Dq;
    float s = 0.f;
    for (int d = t; d < Dq; d += 256) s += x[d];
    red[t] = s; __syncthreads();
    for (int o = 128; o > 0; o >>= 1) { if (t < o) red[t] += red[t + o]; __syncthreads(); }
    float mean = red[0] * (1.0f / Dq);
    __syncthreads();
    float sq = 0.f;
    for (int d = t; d < Dq; d += 256) { float c = x[d] - mean; sq += c * c; }
    red[t] = sq; __syncthreads();
    for (int o = 128; o > 0; o >>= 1) { if (t < o) red[t] += red[t + o]; __syncthreads(); }
    float rstd = rsqrtf(red[0] * (1.0f / Dq) + 1e-5f);
    for (int d = t; d < Dq; d += 256)
        out[(size_t)row * Dq + d] = (x[d] - mean) * rstd * g[d] + b[d];
}

// ---------------- 64x64x16 tiled GEMM (small N cases, guarded) ----------------
__global__ __launch_bounds__(256) void gemm64(const float* __restrict__ A,
                                              const float* __restrict__ Bm,
                                              float* __restrict__ C,
                                              int N, int K) {
    __shared__ float As[16][68];
    __shared__ float Bs[16][64];
    int tid = threadIdx.x;
    int m0 = blockIdx.y * 64, n0 = blockIdx.x * 64;
    int am = tid >> 2, ak = (tid & 3) * 4;
    int bk = tid >> 4, bn = (tid & 15) * 4;
    int ty = tid >> 4, tx = tid & 15;
    float acc[4][4] = {};
    for (int k0 = 0; k0 < K; k0 += 16) {
        float4 av = *(const float4*)(A + (size_t)(m0 + am) * K + k0 + ak);
        float4 bv = make_float4(0.f, 0.f, 0.f, 0.f);
        if (n0 + bn + 4 <= N) bv = *(const float4*)(Bm + (size_t)(k0 + bk) * N + n0 + bn);
        As[ak][am] = av.x; As[ak + 1][am] = av.y; As[ak + 2][am] = av.z; As[ak + 3][am] = av.w;
        *(float4*)&Bs[bk][bn] = bv;
        __syncthreads();
#pragma unroll
        for (int k = 0; k < 16; k++) {
            float4 a = *(const float4*)&As[k][ty * 4];
            float4 b = *(const float4*)&Bs[k][tx * 4];
            acc[0][0] += a.x * b.x; acc[0][1] += a.x * b.y; acc[0][2] += a.x * b.z; acc[0][3] += a.x * b.w;
            acc[1][0] += a.y * b.x; acc[1][1] += a.y * b.y; acc[1][2] += a.y * b.z; acc[1][3] += a.y * b.w;
            acc[2][0] += a.z * b.x; acc[2][1] += a.z * b.y; acc[2][2] += a.z * b.z; acc[2][3] += a.z * b.w;
            acc[3][0] += a.w * b.x; acc[3][1] += a.w * b.y; acc[3][2] += a.w * b.z; acc[3][3] += a.w * b.w;
        }
        __syncthreads();
    }
#pragma unroll
    for (int i = 0; i < 4; i++) {
        int mg = m0 + ty * 4 + i;
#pragma unroll
        for (int j = 0; j < 4; j++) {
            int ng = n0 + tx * 4 + j;
            if (ng < N) C[(size_t)mg * N + ng] = acc[i][j];
        }
    }
}

// ---------------- 128x128x8 double-buffered SGEMM with f32x2 core ----------
// MODE 0: C = A@B                         (plain)
// MODE 1: C = extra + A@B + bias          (out-proj + residual)
// MODE 2: gathered rows (p>>1), C[p] = gelu(A@B + bias_e)   (MoE fc)
// MODE 3: gathered rows p,     C[p] = extra[p]*(A@B + bias_e) (MoE proj)
template<int MODE>
__global__ __launch_bounds__(256) void gemm128(
    const float* __restrict__ A, const float* __restrict__ Bm, float* __restrict__ C,
    int N, int K,
    const float* __restrict__ bias, const float* __restrict__ extra,
    const int* __restrict__ lists, const int* __restrict__ counts)
{
    __shared__ __align__(16) float As[2][8][128];
    __shared__ __align__(16) float Bs[2][8][128];
    __shared__ int sp[128];
    int tid = threadIdx.x;
    int n0 = blockIdx.x * 128;
    int m0 = blockIdx.y * 128;
    const float* Bb = Bm;
    const float* biasb = bias;
    if (MODE >= 2) {
        int e = blockIdx.z;
        int cnt = counts[e];
        if (m0 >= cnt) return;
        if (tid < 128) { int r = m0 + tid; sp[tid] = (r < cnt) ? lists[e * NTOK + r] : -1; }
        Bb = Bm + (size_t)e * K * N;
        biasb = bias + (size_t)e * N;
        __syncthreads();
    }
    int ar = tid >> 1, ac = (tid & 1) * 4;
    int bk = tid >> 5, bn = (tid & 31) * 4;
    const float* arow;
    if (MODE == 2) { int p = sp[ar]; arow = (p >= 0) ? A + (size_t)(p >> 1) * K : nullptr; }
    else if (MODE == 3) { int p = sp[ar]; arow = (p >= 0) ? A + (size_t)p * K : nullptr; }
    else arow = A + (size_t)(m0 + ar) * K;

    float4 av = arow ? *(const float4*)(arow + ac) : make_float4(0.f, 0.f, 0.f, 0.f);
    float4 bv = *(const float4*)(Bb + (size_t)bk * N + n0 + bn);
    As[0][ac][ar] = av.x; As[0][ac + 1][ar] = av.y; As[0][ac + 2][ar] = av.z; As[0][ac + 3][ar] = av.w;
    *(float4*)&Bs[0][bk][bn] = bv;
    __syncthreads();

    int ty = tid >> 4, tx = tid & 15;
    ull acc2[8][4];
#pragma unroll
    for (int i = 0; i < 8; i++)
#pragma unroll
        for (int j = 0; j < 4; j++) acc2[i][j] = 0ull;

    int KT = K >> 3;
    int buf = 0;
    for (int kt = 0; kt < KT; kt++) {
        if (kt + 1 < KT) {
            int k0 = (kt + 1) << 3;
            av = arow ? *(const float4*)(arow + k0 + ac) : make_float4(0.f, 0.f, 0.f, 0.f);
            bv = *(const float4*)(Bb + (size_t)(k0 + bk) * N + n0 + bn);
        }
#pragma unroll
        for (int k = 0; k < 8; k++) {
            float4 a0 = *(const float4*)&As[buf][k][ty * 8];
            float4 a1 = *(const float4*)&As[buf][k][ty * 8 + 4];
            longlong2 bl0 = *(const longlong2*)&Bs[buf][k][tx * 8];
            longlong2 bl1 = *(const longlong2*)&Bs[buf][k][tx * 8 + 4];
            ull b2[4] = { (ull)bl0.x, (ull)bl0.y, (ull)bl1.x, (ull)bl1.y };
            float a[8] = { a0.x, a0.y, a0.z, a0.w, a1.x, a1.y, a1.z, a1.w };
#pragma unroll
            for (int i = 0; i < 8; i++) {
                ull aa = pack2(a[i], a[i]);
#pragma unroll
                for (int j = 0; j < 4; j++) fma2(acc2[i][j], aa, b2[j]);
            }
        }
        if (kt + 1 < KT) {
            buf ^= 1;
            As[buf][ac][ar] = av.x; As[buf][ac + 1][ar] = av.y;
            As[buf][ac + 2][ar] = av.z; As[buf][ac + 3][ar] = av.w;
            *(float4*)&Bs[buf][bk][bn] = bv;
        }
        __syncthreads();
    }

#pragma unroll
    for (int i = 0; i < 8; i++) {
        int mi = ty * 8 + i;
        float accf[8];
#pragma unroll
        for (int j = 0; j < 4; j++) unpack2(acc2[i][j], accf[2 * j], accf[2 * j + 1]);
        if (MODE <= 1) {
            size_t row = (size_t)(m0 + mi) * N;
#pragma unroll
            for (int j = 0; j < 8; j += 4) {
                int ng = n0 + tx * 8 + j;
                float4 r;
                r.x = accf[j]; r.y = accf[j + 1]; r.z = accf[j + 2]; r.w = accf[j + 3];
                if (MODE == 1) {
                    const float4 xr = *(const float4*)(extra + row + ng);
                    r.x += xr.x + bias[ng]; r.y += xr.y + bias[ng + 1];
                    r.z += xr.z + bias[ng + 2]; r.w += xr.w + bias[ng + 3];
                }
                *(float4*)(C + row + ng) = r;
            }
        } else {
            int p = sp[mi];
            if (p < 0) continue;
            float* dst = C + (size_t)p * N;
            int ng = n0 + tx * 8;
            if (MODE == 2) {
#pragma unroll
                for (int j = 0; j < 8; j++) dst[ng + j] = gelu_f(accf[j] + biasb[ng + j]);
            } else {
                float gv = extra[p];
#pragma unroll
                for (int j = 0; j < 8; j++) dst[ng + j] = gv * (accf[j] + biasb[ng + j]);
            }
        }
    }
}

// ---------------- RoPE ----------------
__global__ void rope_kernel(float* buf, int nheads, int total) {
    int idx = blockIdx.x * blockDim.x + threadIdx.x;
    if (idx >= total) return;
    int i    = idx & 31;
    int rest = idx >> 5;
    int head = rest % nheads;
    int tok  = rest / nheads;
    int s    = tok % Sq;
    float inv = powf(10000.0f, -(float)(2 * i) / 64.0f);
    float fr  = (float)s * inv;
    float c = cosf(fr), sn = sinf(fr);
    size_t base = ((size_t)tok * nheads + head) * 64 + 2 * i;
    float x1 = buf[base], x2 = buf[base + 1];
    buf[base]     = x1 * c - x2 * sn;
    buf[base + 1] = x1 * sn + x2 * c;
}

// ---------------- split packed KV ----------------
__global__ void split_kv(const float* __restrict__ kvfull, float* __restrict__ k,
                         float* __restrict__ v) {
    int idx = blockIdx.x * blockDim.x + threadIdx.x;
    if (idx >= NTOK * KVHq * HDq) return;
    int hd = idx & 63; int rest = idx >> 6; int kvh = rest & 3; int tok = rest >> 2;
    size_t src = (size_t)tok * 512 + kvh * 128 + hd * 2;
    k[idx] = kvfull[src];
    v[idx] = kvfull[src + 1];
}

// ---------------- flash attention with f32x2 core ----------------
__global__ __launch_bounds__(64) void flash_kernel(const float* __restrict__ q,
                                                   const float* __restrict__ kb,
                                                   const float* __restrict__ vb,
                                                   float* __restrict__ o) {
    int qt = blockIdx.x, h = blockIdx.y, b = blockIdx.z;
    int t = threadIdx.x;
    int qi = qt * 64 + t;
    __shared__ __align__(16) float sk[64][64];
    __shared__ __align__(16) float sv[64][64];
    __shared__ float ss[64][64];
    ull q2[32];
    const float* qrow = q + (((size_t)b * Sq + qi) * Hq + h) * HDq;
#pragma unroll
    for (int d = 0; d < 64; d += 2) q2[d >> 1] = pack2(qrow[d] * 0.125f, qrow[d + 1] * 0.125f);
    ull acc2[32];
#pragma unroll
    for (int d = 0; d < 32; d++) acc2[d] = 0ull;
    float m = -1e30f, l = 0.f;
    int kvh = h >> 2;
    for (int kt = 0; kt <= qt; kt++) {
        const float* kbase = kb + (((size_t)b * Sq + kt * 64 + t) * KVHq + kvh) * HDq;
        const float* vbase = vb + (((size_t)b * Sq + kt * 64 + t) * KVHq + kvh) * HDq;
#pragma unroll 16
        for (int d = 0; d < 64; d += 4) {
            *(float4*)&sk[t][d] = *(const float4*)(kbase + d);
            *(float4*)&sv[t][d] = *(const float4*)(vbase + d);
        }
        __syncthreads();
        int jend = qi - kt * 64 + 1; if (jend > 64) jend = 64;
        float tmax = -1e30f;
        for (int j = 0; j < jend; j++) {
            const longlong2* k2 = (const longlong2*)&sk[j][0];
            ull s0 = 0ull, s1 = 0ull, s2 = 0ull, s3 = 0ull;
#pragma unroll
            for (int d = 0; d < 8; d++) {
                longlong2 ka = k2[2 * d], kb2 = k2[2 * d + 1];
                fma2(s0, q2[4 * d],     (ull)ka.x);
                fma2(s1, q2[4 * d + 1], (ull)ka.y);
                fma2(s2, q2[4 * d + 2], (ull)kb2.x);
                fma2(s3, q2[4 * d + 3], (ull)kb2.y);
            }
            float a0, a1, b0, b1, c0, c1, d0, d1;
            unpack2(s0, a0, a1); unpack2(s1, b0, b1);
            unpack2(s2, c0, c1); unpack2(s3, d0, d1);
            float s = ((a0 + a1) + (b0 + b1)) + ((c0 + c1) + (d0 + d1));
            ss[j][t] = s;
            tmax = fmaxf(tmax, s);
        }
        float mn = fmaxf(m, tmax);
        float corr = expf(m - mn);
        l *= corr;
        ull corr2 = pack2(corr, corr);
#pragma unroll
        for (int d = 0; d < 32; d++) mul2(acc2[d], corr2);
        for (int j = 0; j < jend; j++) {
            float p = expf(ss[j][t] - mn);
            l += p;
            ull p2 = pack2(p, p);
            const longlong2* v2 = (const longlong2*)&sv[j][0];
#pragma unroll
            for (int d = 0; d < 16; d++) {
                longlong2 vv = v2[d];
                fma2(acc2[2 * d],     p2, (ull)vv.x);
                fma2(acc2[2 * d + 1], p2, (ull)vv.y);
            }
        }
        m = mn;
        __syncthreads();
    }
    float invl = 1.f / l;
    float* orow = o + (((size_t)b * Sq + qi) * Hq + h) * HDq;
#pragma unroll
    for (int d = 0; d < 32; d++) {
        float lo, hi; unpack2(acc2[d], lo, hi);
        orow[2 * d] = lo * invl;
        orow[2 * d + 1] = hi * invl;
    }
}

// ---------------- zero expert counters ----------------
__global__ void zero_counts(int* c) { if (threadIdx.x < Eq) c[threadIdx.x] = 0; }

// ---------------- router ----------------
__global__ void router_kernel(const float* __restrict__ h2, const float* __restrict__ rw,
                              float* __restrict__ logits, float* __restrict__ gate,
                              int* __restrict__ lists, int* __restrict__ counts) {
    int tok = blockIdx.x * blockDim.x + threadIdx.x;
    if (tok >= NTOK) return;
    float l[8];
#pragma unroll
    for (int e = 0; e < 8; e++) l[e] = 0.f;
    const float* hr = h2 + (size_t)tok * Dq;
    for (int k = 0; k < Dq; k++) {
        float hv = hr[k];
#pragma unroll
        for (int e = 0; e < 8; e++) l[e] += hv * rw[k * 8 + e];
    }
#pragma unroll
    for (int e = 0; e < 8; e++) logits[(size_t)tok * 8 + e] = l[e];
    int i0 = 0;
#pragma unroll
    for (int e = 1; e < 8; e++) if (l[e] > l[i0]) i0 = e;
    int i1 = -1;
#pragma unroll
    for (int e = 0; e < 8; e++) {
        if (e == i0) continue;
        if (i1 < 0 || l[e] > l[i1]) i1 = e;
    }
    float e1 = expf(l[i1] - l[i0]);
    float denom = 1.f / (1.f + e1);
    gate[tok * 2]     = denom;
    gate[tok * 2 + 1] = e1 * denom;
    int pos0 = atomicAdd(&counts[i0], 1);
    lists[i0 * NTOK + pos0] = tok * 2;
    int pos1 = atomicAdd(&counts[i1], 1);
    lists[i1 * NTOK + pos1] = tok * 2 + 1;
}

// ---------------- finalize ----------------
__global__ void finalize_kernel(const float* __restrict__ x1, const float* __restrict__ yb,
                                const float* __restrict__ g, const float* __restrict__ b,
                                float* __restrict__ out) {
    int row = blockIdx.x; int t = threadIdx.x;
    __shared__ float sv[1024];
    __shared__ float red[256];
    float s = 0.f;
    for (int d = t; d < Dq; d += 256) {
        float v = yb[(size_t)(row * 2) * Dq + d] + yb[(size_t)(row * 2 + 1) * Dq + d];
        sv[d] = v;
        s += v;
    }
    red[t] = s; __syncthreads();
    for (int o = 128; o > 0; o >>= 1) { if (t < o) red[t] += red[t + o]; __syncthreads(); }
    float mean = red[0] * (1.0f / Dq);
    __syncthreads();
    float sq = 0.f;
    for (int d = t; d < Dq; d += 256) { float c = sv[d] - mean; sq += c * c; }
    red[t] = sq; __syncthreads();
    for (int o = 128; o > 0; o >>= 1) { if (t < o) red[t] += red[t + o]; __syncthreads(); }
    float rstd = rsqrtf(red[0] * (1.0f / Dq) + 1e-5f);
    for (int d = t; d < Dq; d += 256)
        out[(size_t)row * Dq + d] = x1[(size_t)row * Dq + d] + (sv[d] - mean) * rstd * g[d] + b[d];
}

// ---------------- launch ----------------
extern "C" void kernel_launch(void* const* d_in, const int* in_sizes, int n_in,
                              void* d_out, int out_size) {
    const float* x    = (const float*)d_in[0];
    const float* ln1g = (const float*)d_in[1];
    const float* ln1b = (const float*)d_in[2];
    const float* qaw  = (const float*)d_in[3];
    const float* qbw  = (const float*)d_in[4];
    const float* kvaw = (const float*)d_in[5];
    const float* kvbw = (const float*)d_in[6];
    const float* outw = (const float*)d_in[7];
    const float* outb = (const float*)d_in[8];
    const float* ln2g = (const float*)d_in[9];
    const float* ln2b = (const float*)d_in[10];
    const float* rw   = (const float*)d_in[11];
    const float* fcw  = (const float*)d_in[12];
    const float* fcb  = (const float*)d_in[13];
    const float* pw   = (const float*)d_in[14];
    const float* pb   = (const float*)d_in[15];
    const float* mlng = (const float*)d_in[16];
    const float* mlnb = (const float*)d_in[17];

    float* out1 = (float*)d_out;
    float* out2 = out1 + (size_t)NTOK * Dq;

    float *h, *qlat, *q, *kvlat, *kvfull, *kb, *vb, *ob, *x1, *h2, *hid, *yb, *gate;
    int *lists, *counts;
    cudaGetSymbolAddress((void**)&h, g_h);
    cudaGetSymbolAddress((void**)&qlat, g_qlat);
    cudaGetSymbolAddress((void**)&q, g_q);
    cudaGetSymbolAddress((void**)&kvlat, g_kvlat);
    cudaGetSymbolAddress((void**)&kvfull, g_kvfull);
    cudaGetSymbolAddress((void**)&kb, g_k);
    cudaGetSymbolAddress((void**)&vb, g_v);
    cudaGetSymbolAddress((void**)&ob, g_o);
    cudaGetSymbolAddress((void**)&x1, g_x1);
    cudaGetSymbolAddress((void**)&h2, g_h2);
    cudaGetSymbolAddress((void**)&hid, g_hidden);
    cudaGetSymbolAddress((void**)&yb, g_y);
    cudaGetSymbolAddress((void**)&gate, g_gate);
    cudaGetSymbolAddress((void**)&lists, g_lists);
    cudaGetSymbolAddress((void**)&counts, g_counts);

    // 1. LN1
    ln_kernel<<<NTOK, 256>>>(x, ln1g, ln1b, h);
    // 2. q = (h @ q_a) @ q_b
    gemm64<<<dim3(1, NTOK / 64), 256>>>(h, qaw, qlat, QLATq, Dq);
    gemm128<0><<<dim3(Dq / 128, NTOK / 128), 256>>>(qlat, qbw, q, Dq, QLATq,
                                                    nullptr, nullptr, nullptr, nullptr);
    // 3. kv = (h @ kv_a) @ kv_b
    gemm64<<<dim3(1, NTOK / 64), 256>>>(h, kvaw, kvlat, KVLATq, Dq);
    gemm64<<<dim3(8, NTOK / 64), 256>>>(kvlat, kvbw, kvfull, 512, KVLATq);
    // 4. RoPE q, split kv, RoPE k
    rope_kernel<<<(NTOK * Hq * 32 + 255) / 256, 256>>>(q, Hq, NTOK * Hq * 32);
    split_kv<<<(NTOK * KVHq * HDq + 255) / 256, 256>>>(kvfull, kb, vb);
    rope_kernel<<<(NTOK * KVHq * 32 + 255) / 256, 256>>>(kb, KVHq, NTOK * KVHq * 32);
    // 5. attention
    flash_kernel<<<dim3(Sq / 64, Hq, Bq), 64>>>(q, kb, vb, ob);
    // 6. out proj + residual
    gemm128<1><<<dim3(Dq / 128, NTOK / 128), 256>>>(ob, outw, x1, Dq, Dq,
                                                    outb, x, nullptr, nullptr);
    // 7. LN2
    ln_kernel<<<NTOK, 256>>>(x1, ln2g, ln2b, h2);
    // 8. router
    zero_counts<<<1, 32>>>(counts);
    router_kernel<<<NTOK / 256, 256>>>(h2, rw, out2, gate, lists, counts);
    // 9. MoE
    gemm128<2><<<dim3(FFq / 128, NTOK / 128, Eq), 256>>>(h2, fcw, hid, FFq, Dq,
                                                         fcb, nullptr, lists, counts);
    gemm128<3><<<dim3(Dq / 128, NTOK / 128, Eq), 256>>>(hid, pw, yb, Dq, FFq,
                                                        pb, gate, lists, counts);
    // 10. finalize
    finalize_kernel<<<NTOK, 256>>>(x1, yb, mlng, mlnb, out1);
}